// round 2
// baseline (speedup 1.0000x reference)
#include <cuda_runtime.h>
#include <math.h>

// Problem constants
constexpr int B_  = 8;
constexpr int S_  = 8192;
constexpr int H_  = 256;
constexpr int NCH = 16;            // split-K chunks for the forward DFT GEMM
constexpr int KCH = S_ / NCH;      // 512

// ---------------------------------------------------------------------------
// Scratch (device globals — no allocation allowed)
// ---------------------------------------------------------------------------
__device__ float g_E2[128 * 8192];        // fwd DFT basis: rows 0-63 cos, 64-127 -sin
__device__ float g_G [8192 * 128];        // inv DFT basis: cols 0-63 cos/S, 64-127 -sin/S
__device__ float g_part[128 * 128 * 256]; // split-K partials for UT (NCH*B blocks)
__device__ float g_UT[8 * 128 * 256];     // ut: [b][m<64: re | m+64: im][h]
__device__ float g_S [8 * 128 * 256];     // s = gelu(Wu): same layout
__device__ float g_D [8 * 128 * 256];     // conv: [b][k<64: re | k+64: im][h]
__device__ float g_spec[8 * 8192 * 256];  // inverse-transform result
__device__ float g_act [8 * 8192 * 256];  // gelu(spec + skip)
__device__ float g_h   [8 * 8192 * 128];  // mlp hidden

__device__ __forceinline__ float gelu1(float x) {
    return 0.5f * x * (1.0f + erff(x * 0.7071067811865476f));
}

// ---------------------------------------------------------------------------
// K0: build DFT basis tables (runs every launch; deterministic)
// ---------------------------------------------------------------------------
__global__ void k_tables() {
    int idx = blockIdx.x * blockDim.x + threadIdx.x;
    if (idx >= 128 * 8192) return;
    const float W = 7.669903939428206e-4f;  // 2*pi/8192

    // E2[m][s], idx = m*8192 + s
    {
        int m = idx >> 13, s = idx & 8191;
        int mm = m & 63;
        int ph = (mm * s) & 8191;
        float a = (float)(ph >= 4096 ? ph - 8192 : ph) * W;
        float sn, cs;
        __sincosf(a, &sn, &cs);
        g_E2[idx] = (m < 64) ? cs : -sn;
    }
    // G[s][k], idx = s*128 + k
    {
        int s = idx >> 7, k = idx & 127;
        int km = k & 63;
        int ph = (km * s) & 8191;
        float a = (float)(ph >= 4096 ? ph - 8192 : ph) * W;
        float sn, cs;
        __sincosf(a, &sn, &cs);
        g_G[idx] = ((k < 64) ? cs : -sn) * (1.0f / 8192.0f);
    }
}

// ---------------------------------------------------------------------------
// K2: reduce split-K partials -> g_UT
// ---------------------------------------------------------------------------
__global__ void k_reduce() {
    int idx = blockIdx.x * 256 + threadIdx.x;      // < 8*128*256 = 262144
    int b  = idx >> 15;
    int rh = idx & 32767;
    const float* p = g_part + (size_t)b * (NCH * 32768) + rh;
    float s = 0.f;
#pragma unroll
    for (int c = 0; c < NCH; c++) s += p[(size_t)c * 32768];
    g_UT[idx] = s;
}

// ---------------------------------------------------------------------------
// K3: per-mode complex mix Wu = ut @ (Wr + i Wi), then s = gelu(.) per part
// grid: (2 halves of H', 64 modes), 256 threads
// ---------------------------------------------------------------------------
__global__ __launch_bounds__(256) void k_modemix(const float* __restrict__ Wr,
                                                 const float* __restrict__ Wi) {
    __shared__ float utr[8 * 256];
    __shared__ float uti[8 * 256];
    int m  = blockIdx.y;
    int H0 = blockIdx.x * 128;
    int t  = threadIdx.x;

    for (int i = t; i < 2048; i += 256) {
        int b = i >> 8, h = i & 255;
        utr[i] = g_UT[((size_t)b * 128 + m) * 256 + h];
        uti[i] = g_UT[((size_t)b * 128 + 64 + m) * 256 + h];
    }
    __syncthreads();

    int b = t >> 5, lane = t & 31;
    int Hc = H0 + lane * 4;
    float4 ar = {0, 0, 0, 0}, ai = {0, 0, 0, 0};
    const float* wrp = Wr + (size_t)m * 256 * 256 + Hc;
    const float* wip = Wi + (size_t)m * 256 * 256 + Hc;
    const float* ur = utr + b * 256;
    const float* ui = uti + b * 256;

#pragma unroll 4
    for (int h = 0; h < 256; h++) {
        float a = ur[h], c = ui[h];
        float4 wr = *(const float4*)(wrp + (size_t)h * 256);
        float4 wi = *(const float4*)(wip + (size_t)h * 256);
        ar.x += a * wr.x - c * wi.x;  ar.y += a * wr.y - c * wi.y;
        ar.z += a * wr.z - c * wi.z;  ar.w += a * wr.w - c * wi.w;
        ai.x += a * wi.x + c * wr.x;  ai.y += a * wi.y + c * wr.y;
        ai.z += a * wi.z + c * wr.z;  ai.w += a * wi.w + c * wr.w;
    }
    float4 sr, si;
    sr.x = gelu1(ar.x); sr.y = gelu1(ar.y); sr.z = gelu1(ar.z); sr.w = gelu1(ar.w);
    si.x = gelu1(ai.x); si.y = gelu1(ai.y); si.z = gelu1(ai.z); si.w = gelu1(ai.w);
    *(float4*)&g_S[((size_t)b * 128 + m) * 256 + Hc]      = sr;
    *(float4*)&g_S[((size_t)b * 128 + 64 + m) * 256 + Hc] = si;
}

// ---------------------------------------------------------------------------
// K4: circular convolution along modes (length 64), scaled by 1/sqrt(64)=1/8
// grid: (64 h-tiles of 4, 8 batches), 256 threads = 4h x 64k
// ---------------------------------------------------------------------------
__global__ __launch_bounds__(256) void k_conv() {
    __shared__ float2 utc[4][64];
    __shared__ float2 sc[4][64];
    int b  = blockIdx.y;
    int h0 = blockIdx.x * 4;
    int t  = threadIdx.x;

    {
        int hh = t >> 6, mj = t & 63;
        int h = h0 + hh;
        utc[hh][mj] = make_float2(g_UT[((size_t)b * 128 + mj) * 256 + h],
                                  g_UT[((size_t)b * 128 + 64 + mj) * 256 + h]);
        sc[hh][mj]  = make_float2(g_S[((size_t)b * 128 + mj) * 256 + h],
                                  g_S[((size_t)b * 128 + 64 + mj) * 256 + h]);
    }
    __syncthreads();

    int hh = t >> 6, k = t & 63;
    float cr = 0.f, ci = 0.f;
#pragma unroll 8
    for (int j = 0; j < 64; j++) {
        float2 a = utc[hh][j];
        float2 s = sc[hh][(k - j) & 63];
        cr += a.x * s.x - a.y * s.y;
        ci += a.x * s.y + a.y * s.x;
    }
    int h = h0 + hh;
    g_D[((size_t)b * 128 + k) * 256 + h]      = cr * 0.125f;
    g_D[((size_t)b * 128 + 64 + k) * 256 + h] = ci * 0.125f;
}

// ---------------------------------------------------------------------------
// Generic fp32 GEMM, 128x128 tile, BK=16, 8x8 per thread, 256 threads.
// MODE 0: UTpart = E2 @ u (NN, split-K, z = b*NCH+chunk)
// MODE 1: spec   = G @ D_b (NN, z = b)
// MODE 2: act    = gelu(u @ skip_w^T + skip_b + spec)  (TN)
// MODE 3: h      = gelu(act @ w1^T + b1)               (TN)
// MODE 4: out    = h @ w2^T + b2                       (TN)
// ---------------------------------------------------------------------------
template <int MODE>
__global__ __launch_bounds__(256) void k_gemm(const float* __restrict__ Ax,
                                              const float* __restrict__ Bx,
                                              const float* __restrict__ biasx,
                                              float* __restrict__ Cx) {
    constexpr bool BT   = (MODE >= 2);
    constexpr bool ADD  = (MODE == 2);
    constexpr bool BIAS = (MODE >= 2);
    constexpr bool GEL  = (MODE == 2 || MODE == 3);
    constexpr int K   = (MODE == 0) ? KCH : (MODE == 1) ? 128 : (MODE == 4) ? 128 : 256;
    constexpr int lda = (MODE == 0) ? 8192 : (MODE == 1) ? 128 : (MODE == 4) ? 128 : 256;
    constexpr int ldb = (MODE == 4) ? 128 : 256;
    constexpr int ldc = (MODE == 3) ? 128 : 256;

    const float* A;
    const float* Bp;
    float* C;
    const float* Addp = nullptr;
    int z = blockIdx.z;

    if constexpr (MODE == 0) {
        int b = z / NCH, c = z % NCH;
        A  = g_E2 + c * KCH;
        Bp = Bx + (size_t)b * (S_ * H_) + (size_t)c * (KCH * H_);
        C  = g_part + (size_t)z * (128 * 256);
    } else if constexpr (MODE == 1) {
        A  = g_G;
        Bp = g_D + (size_t)z * (128 * 256);
        C  = g_spec + (size_t)z * (S_ * H_);
    } else if constexpr (MODE == 2) {
        A = Ax; Bp = Bx; C = g_act; Addp = g_spec;
    } else if constexpr (MODE == 3) {
        A = g_act; Bp = Bx; C = g_h;
    } else {
        A = g_h; Bp = Bx; C = Cx;
    }

    __shared__ float As[16][128];
    __shared__ float Bs[16][128];

    int t  = threadIdx.x;
    int m0 = blockIdx.y * 128;
    int n0 = blockIdx.x * 128;
    int tx = t & 15, ty = t >> 4;

    float acc[8][8];
#pragma unroll
    for (int i = 0; i < 8; i++)
#pragma unroll
        for (int j = 0; j < 8; j++) acc[i][j] = 0.f;

    for (int kt = 0; kt < K; kt += 16) {
        // A tile -> As[kk][row]
#pragma unroll
        for (int i = 0; i < 2; i++) {
            int id = t + i * 256;
            int row = id >> 2, kq = id & 3;
            float4 v = *(const float4*)(A + (size_t)(m0 + row) * lda + kt + kq * 4);
            As[kq * 4 + 0][row] = v.x;
            As[kq * 4 + 1][row] = v.y;
            As[kq * 4 + 2][row] = v.z;
            As[kq * 4 + 3][row] = v.w;
        }
        // B tile -> Bs[kk][col]
#pragma unroll
        for (int i = 0; i < 2; i++) {
            int id = t + i * 256;
            if constexpr (!BT) {
                int kk = id >> 5, cq = id & 31;
                float4 v = *(const float4*)(Bp + (size_t)(kt + kk) * ldb + n0 + cq * 4);
                *(float4*)&Bs[kk][cq * 4] = v;
            } else {
                int col = id >> 2, kq = id & 3;
                float4 v = *(const float4*)(Bp + (size_t)(n0 + col) * ldb + kt + kq * 4);
                Bs[kq * 4 + 0][col] = v.x;
                Bs[kq * 4 + 1][col] = v.y;
                Bs[kq * 4 + 2][col] = v.z;
                Bs[kq * 4 + 3][col] = v.w;
            }
        }
        __syncthreads();
#pragma unroll
        for (int kk = 0; kk < 16; kk++) {
            float a[8], bb[8];
            *(float4*)&a[0]  = *(const float4*)&As[kk][ty * 8];
            *(float4*)&a[4]  = *(const float4*)&As[kk][ty * 8 + 4];
            *(float4*)&bb[0] = *(const float4*)&Bs[kk][tx * 8];
            *(float4*)&bb[4] = *(const float4*)&Bs[kk][tx * 8 + 4];
#pragma unroll
            for (int i = 0; i < 8; i++)
#pragma unroll
                for (int j = 0; j < 8; j++) acc[i][j] += a[i] * bb[j];
        }
        __syncthreads();
    }

    // epilogue
#pragma unroll
    for (int i = 0; i < 8; i++) {
        int row = m0 + ty * 8 + i;
#pragma unroll
        for (int jq = 0; jq < 2; jq++) {
            int col = n0 + tx * 8 + jq * 4;
            float4 v;
            v.x = acc[i][jq * 4 + 0];
            v.y = acc[i][jq * 4 + 1];
            v.z = acc[i][jq * 4 + 2];
            v.w = acc[i][jq * 4 + 3];
            if constexpr (BIAS) {
                float4 bi = *(const float4*)(biasx + col);
                v.x += bi.x; v.y += bi.y; v.z += bi.z; v.w += bi.w;
            }
            if constexpr (ADD) {
                float4 ad = *(const float4*)(Addp + (size_t)row * 256 + col);
                v.x += ad.x; v.y += ad.y; v.z += ad.z; v.w += ad.w;
            }
            if constexpr (GEL) {
                v.x = gelu1(v.x); v.y = gelu1(v.y);
                v.z = gelu1(v.z); v.w = gelu1(v.w);
            }
            *(float4*)(C + (size_t)row * ldc + col) = v;
        }
    }
}

// ---------------------------------------------------------------------------
// Launch
// ---------------------------------------------------------------------------
extern "C" void kernel_launch(void* const* d_in, const int* in_sizes, int n_in,
                              void* d_out, int out_size) {
    const float* u      = (const float*)d_in[0];
    const float* Wr     = (const float*)d_in[1];
    const float* Wi     = (const float*)d_in[2];
    const float* skip_w = (const float*)d_in[3];
    const float* skip_b = (const float*)d_in[4];
    const float* w1     = (const float*)d_in[5];
    const float* b1     = (const float*)d_in[6];
    const float* w2     = (const float*)d_in[7];
    const float* b2     = (const float*)d_in[8];
    float* out = (float*)d_out;

    k_tables<<<4096, 256>>>();
    k_gemm<0><<<dim3(2, 1, 8 * NCH), 256>>>(nullptr, u, nullptr, nullptr); // UT partials
    k_reduce<<<1024, 256>>>();                                             // UT
    k_modemix<<<dim3(2, 64), 256>>>(Wr, Wi);                               // s = gelu(Wu)
    k_conv<<<dim3(64, 8), 256>>>();                                        // circular conv
    k_gemm<1><<<dim3(2, 64, 8), 256>>>(nullptr, nullptr, nullptr, nullptr); // spec
    k_gemm<2><<<dim3(2, 512, 1), 256>>>(u, skip_w, skip_b, nullptr);       // act
    k_gemm<3><<<dim3(1, 512, 1), 256>>>(nullptr, w1, b1, nullptr);         // h
    k_gemm<4><<<dim3(2, 512, 1), 256>>>(nullptr, w2, b2, out);             // out
}

// round 3
// speedup vs baseline: 1.1028x; 1.1028x over previous
#include <cuda_runtime.h>
#include <math.h>

// Problem constants
constexpr int B_  = 8;
constexpr int S_  = 8192;
constexpr int H_  = 256;
constexpr int NCH = 16;            // split-K chunks for the forward DFT GEMM
constexpr int KCH = S_ / NCH;      // 512

// ---------------------------------------------------------------------------
// Scratch (device globals — no allocation allowed)
// ---------------------------------------------------------------------------
__device__ float g_E2[128 * 8192];        // fwd DFT basis: rows 0-63 cos, 64-127 -sin
__device__ float g_G [8192 * 128];        // inv DFT basis: cols 0-63 cos/S, 64-127 -sin/S
__device__ float g_part[128 * 128 * 256]; // split-K partials for UT (NCH*B blocks)
__device__ float g_UT[8 * 128 * 256];     // ut: [b][m<64: re | m+64: im][h]
__device__ float g_S [8 * 128 * 256];     // s = gelu(Wu): same layout
__device__ float g_D [8 * 128 * 256];     // conv: [b][k<64: re | k+64: im][h]
__device__ float g_spec[8 * 8192 * 256];  // inverse-transform result
__device__ float g_act [8 * 8192 * 256];  // gelu(spec + skip)
__device__ float g_h   [8 * 8192 * 128];  // mlp hidden

__device__ __forceinline__ float gelu1(float x) {
    return 0.5f * x * (1.0f + erff(x * 0.7071067811865476f));
}

// ---------------------------------------------------------------------------
// K0: build DFT basis tables (runs every launch; deterministic)
// ---------------------------------------------------------------------------
__global__ void k_tables() {
    int idx = blockIdx.x * blockDim.x + threadIdx.x;
    if (idx >= 128 * 8192) return;
    const float W = 7.669903939428206e-4f;  // 2*pi/8192

    // E2[m][s], idx = m*8192 + s
    {
        int m = idx >> 13, s = idx & 8191;
        int mm = m & 63;
        int ph = (mm * s) & 8191;
        float a = (float)(ph >= 4096 ? ph - 8192 : ph) * W;
        float sn, cs;
        __sincosf(a, &sn, &cs);
        g_E2[idx] = (m < 64) ? cs : -sn;
    }
    // G[s][k], idx = s*128 + k
    {
        int s = idx >> 7, k = idx & 127;
        int km = k & 63;
        int ph = (km * s) & 8191;
        float a = (float)(ph >= 4096 ? ph - 8192 : ph) * W;
        float sn, cs;
        __sincosf(a, &sn, &cs);
        g_G[idx] = ((k < 64) ? cs : -sn) * (1.0f / 8192.0f);
    }
}

// ---------------------------------------------------------------------------
// K2: reduce split-K partials -> g_UT
// ---------------------------------------------------------------------------
__global__ void k_reduce() {
    int idx = blockIdx.x * 256 + threadIdx.x;      // < 8*128*256 = 262144
    int b  = idx >> 15;
    int rh = idx & 32767;
    const float* p = g_part + (size_t)b * (NCH * 32768) + rh;
    float s = 0.f;
#pragma unroll
    for (int c = 0; c < NCH; c++) s += p[(size_t)c * 32768];
    g_UT[idx] = s;
}

// ---------------------------------------------------------------------------
// K3: per-mode complex mix Wu = ut @ (Wr + i Wi), then s = gelu(.) per part
// grid: (8 col-tiles of 32, 64 modes), 256 threads = 32 cols x 8 batches
// Memory-bound: 33.5 MB of W read once, coalesced 128B rows per warp.
// ---------------------------------------------------------------------------
__global__ __launch_bounds__(256) void k_modemix(const float* __restrict__ Wr,
                                                 const float* __restrict__ Wi) {
    __shared__ float utr[8][256];
    __shared__ float uti[8][256];
    int m  = blockIdx.y;
    int H0 = blockIdx.x * 32;
    int t  = threadIdx.x;

    for (int i = t; i < 2048; i += 256) {
        int b = i >> 8, h = i & 255;
        utr[b][h] = g_UT[((size_t)b * 128 + m) * 256 + h];
        uti[b][h] = g_UT[((size_t)b * 128 + 64 + m) * 256 + h];
    }
    __syncthreads();

    int col = H0 + (t & 31);
    int b   = t >> 5;
    const float* wrp = Wr + (size_t)m * 65536 + col;
    const float* wip = Wi + (size_t)m * 65536 + col;

    float ar = 0.f, ai = 0.f;
#pragma unroll 8
    for (int h = 0; h < 256; h++) {
        float wr = wrp[(size_t)h * 256];
        float wi = wip[(size_t)h * 256];
        float a = utr[b][h], c = uti[b][h];
        ar += a * wr - c * wi;
        ai += a * wi + c * wr;
    }
    g_S[((size_t)b * 128 + m) * 256 + col]      = gelu1(ar);
    g_S[((size_t)b * 128 + 64 + m) * 256 + col] = gelu1(ai);
}

// ---------------------------------------------------------------------------
// K4: circular convolution along modes (length 64), scaled by 1/sqrt(64)=1/8
// ---------------------------------------------------------------------------
__global__ __launch_bounds__(256) void k_conv() {
    __shared__ float2 utc[4][64];
    __shared__ float2 sc[4][64];
    int b  = blockIdx.y;
    int h0 = blockIdx.x * 4;
    int t  = threadIdx.x;

    {
        int hh = t >> 6, mj = t & 63;
        int h = h0 + hh;
        utc[hh][mj] = make_float2(g_UT[((size_t)b * 128 + mj) * 256 + h],
                                  g_UT[((size_t)b * 128 + 64 + mj) * 256 + h]);
        sc[hh][mj]  = make_float2(g_S[((size_t)b * 128 + mj) * 256 + h],
                                  g_S[((size_t)b * 128 + 64 + mj) * 256 + h]);
    }
    __syncthreads();

    int hh = t >> 6, k = t & 63;
    float cr = 0.f, ci = 0.f;
#pragma unroll 8
    for (int j = 0; j < 64; j++) {
        float2 a = utc[hh][j];
        float2 s = sc[hh][(k - j) & 63];
        cr += a.x * s.x - a.y * s.y;
        ci += a.x * s.y + a.y * s.x;
    }
    int h = h0 + hh;
    g_D[((size_t)b * 128 + k) * 256 + h]      = cr * 0.125f;
    g_D[((size_t)b * 128 + 64 + k) * 256 + h] = ci * 0.125f;
}

// ---------------------------------------------------------------------------
// Generic fp32 GEMM, 128x128 tile, BK=16, 8x8 per thread, 256 threads.
// Double-buffered smem + register-staged global prefetch; one sync per tile.
// MODE 0: UTpart = E2 @ u (NN, split-K, z = b*NCH+chunk)
// MODE 1: spec   = G @ D_b (NN, z = b)
// MODE 2: act    = gelu(u @ skip_w^T + skip_b + spec)  (TN)
// MODE 3: h      = gelu(act @ w1^T + b1)               (TN)
// MODE 4: out    = h @ w2^T + b2                       (TN)
// ---------------------------------------------------------------------------
template <int MODE>
__global__ __launch_bounds__(256, 2) void k_gemm(const float* __restrict__ Ax,
                                                 const float* __restrict__ Bx,
                                                 const float* __restrict__ biasx,
                                                 float* __restrict__ Cx) {
    constexpr bool BT   = (MODE >= 2);
    constexpr bool ADD  = (MODE == 2);
    constexpr bool BIAS = (MODE >= 2);
    constexpr bool GEL  = (MODE == 2 || MODE == 3);
    constexpr int K   = (MODE == 0) ? KCH : (MODE == 1) ? 128 : (MODE == 4) ? 128 : 256;
    constexpr int lda = (MODE == 0) ? 8192 : (MODE == 1) ? 128 : (MODE == 4) ? 128 : 256;
    constexpr int ldb = (MODE == 4) ? 128 : 256;
    constexpr int ldc = (MODE == 3) ? 128 : 256;
    constexpr int NT  = K / 16;

    const float* A;
    const float* Bp;
    float* C;
    const float* Addp = nullptr;
    int z = blockIdx.z;

    if constexpr (MODE == 0) {
        int b = z / NCH, c = z % NCH;
        A  = g_E2 + c * KCH;
        Bp = Bx + (size_t)b * (S_ * H_) + (size_t)c * (KCH * H_);
        C  = g_part + (size_t)z * (128 * 256);
    } else if constexpr (MODE == 1) {
        A  = g_G;
        Bp = g_D + (size_t)z * (128 * 256);
        C  = g_spec + (size_t)z * (S_ * H_);
    } else if constexpr (MODE == 2) {
        A = Ax; Bp = Bx; C = g_act; Addp = g_spec;
    } else if constexpr (MODE == 3) {
        A = g_act; Bp = Bx; C = g_h;
    } else {
        A = g_h; Bp = Bx; C = Cx;
    }

    __shared__ float As[2][16][128];
    __shared__ float Bs[2][16][128];

    int t  = threadIdx.x;
    int m0 = blockIdx.y * 128;
    int n0 = blockIdx.x * 128;
    int tx = t & 15, ty = t >> 4;

    // per-thread load coordinates
    int a_row0 = t >> 2,        a_kq = t & 3;          // + i*64 rows
    int bn_kk0 = t >> 5,        bn_cq = t & 31;        // NN B: + i*8 kk
    int bt_col0 = t >> 2,       bt_kq = t & 3;         // TN B: + i*64 cols

    float4 va[2], vb[2];

    auto ldA = [&](int kt) {
#pragma unroll
        for (int i = 0; i < 2; i++)
            va[i] = *(const float4*)(A + (size_t)(m0 + a_row0 + i * 64) * lda + kt + a_kq * 4);
    };
    auto stA = [&](int buf) {
#pragma unroll
        for (int i = 0; i < 2; i++) {
            int row = a_row0 + i * 64;
            As[buf][a_kq * 4 + 0][row] = va[i].x;
            As[buf][a_kq * 4 + 1][row] = va[i].y;
            As[buf][a_kq * 4 + 2][row] = va[i].z;
            As[buf][a_kq * 4 + 3][row] = va[i].w;
        }
    };
    auto ldB = [&](int kt) {
#pragma unroll
        for (int i = 0; i < 2; i++) {
            if constexpr (!BT)
                vb[i] = *(const float4*)(Bp + (size_t)(kt + bn_kk0 + i * 8) * ldb + n0 + bn_cq * 4);
            else
                vb[i] = *(const float4*)(Bp + (size_t)(n0 + bt_col0 + i * 64) * ldb + kt + bt_kq * 4);
        }
    };
    auto stB = [&](int buf) {
#pragma unroll
        for (int i = 0; i < 2; i++) {
            if constexpr (!BT) {
                *(float4*)&Bs[buf][bn_kk0 + i * 8][bn_cq * 4] = vb[i];
            } else {
                int col = bt_col0 + i * 64;
                Bs[buf][bt_kq * 4 + 0][col] = vb[i].x;
                Bs[buf][bt_kq * 4 + 1][col] = vb[i].y;
                Bs[buf][bt_kq * 4 + 2][col] = vb[i].z;
                Bs[buf][bt_kq * 4 + 3][col] = vb[i].w;
            }
        }
    };

    float acc[8][8];
#pragma unroll
    for (int i = 0; i < 8; i++)
#pragma unroll
        for (int j = 0; j < 8; j++) acc[i][j] = 0.f;

    ldA(0); ldB(0);
    stA(0); stB(0);
    __syncthreads();

    for (int it = 0; it < NT; it++) {
        int cur = it & 1;
        if (it + 1 < NT) { ldA((it + 1) * 16); ldB((it + 1) * 16); }
#pragma unroll
        for (int kk = 0; kk < 16; kk++) {
            float a[8], bb[8];
            *(float4*)&a[0]  = *(const float4*)&As[cur][kk][ty * 8];
            *(float4*)&a[4]  = *(const float4*)&As[cur][kk][ty * 8 + 4];
            *(float4*)&bb[0] = *(const float4*)&Bs[cur][kk][tx * 8];
            *(float4*)&bb[4] = *(const float4*)&Bs[cur][kk][tx * 8 + 4];
#pragma unroll
            for (int i = 0; i < 8; i++)
#pragma unroll
                for (int j = 0; j < 8; j++) acc[i][j] += a[i] * bb[j];
        }
        if (it + 1 < NT) { stA(cur ^ 1); stB(cur ^ 1); }
        __syncthreads();
    }

    // epilogue
#pragma unroll
    for (int i = 0; i < 8; i++) {
        int row = m0 + ty * 8 + i;
#pragma unroll
        for (int jq = 0; jq < 2; jq++) {
            int col = n0 + tx * 8 + jq * 4;
            float4 v;
            v.x = acc[i][jq * 4 + 0];
            v.y = acc[i][jq * 4 + 1];
            v.z = acc[i][jq * 4 + 2];
            v.w = acc[i][jq * 4 + 3];
            if constexpr (BIAS) {
                float4 bi = *(const float4*)(biasx + col);
                v.x += bi.x; v.y += bi.y; v.z += bi.z; v.w += bi.w;
            }
            if constexpr (ADD) {
                float4 ad = *(const float4*)(Addp + (size_t)row * 256 + col);
                v.x += ad.x; v.y += ad.y; v.z += ad.z; v.w += ad.w;
            }
            if constexpr (GEL) {
                v.x = gelu1(v.x); v.y = gelu1(v.y);
                v.z = gelu1(v.z); v.w = gelu1(v.w);
            }
            *(float4*)(C + (size_t)row * ldc + col) = v;
        }
    }
}

// ---------------------------------------------------------------------------
// Launch
// ---------------------------------------------------------------------------
extern "C" void kernel_launch(void* const* d_in, const int* in_sizes, int n_in,
                              void* d_out, int out_size) {
    const float* u      = (const float*)d_in[0];
    const float* Wr     = (const float*)d_in[1];
    const float* Wi     = (const float*)d_in[2];
    const float* skip_w = (const float*)d_in[3];
    const float* skip_b = (const float*)d_in[4];
    const float* w1     = (const float*)d_in[5];
    const float* b1     = (const float*)d_in[6];
    const float* w2     = (const float*)d_in[7];
    const float* b2     = (const float*)d_in[8];
    float* out = (float*)d_out;

    k_tables<<<4096, 256>>>();
    k_gemm<0><<<dim3(2, 1, 8 * NCH), 256>>>(nullptr, u, nullptr, nullptr); // UT partials
    k_reduce<<<1024, 256>>>();                                             // UT
    k_modemix<<<dim3(8, 64), 256>>>(Wr, Wi);                               // s = gelu(Wu)
    k_conv<<<dim3(64, 8), 256>>>();                                        // circular conv
    k_gemm<1><<<dim3(2, 64, 8), 256>>>(nullptr, nullptr, nullptr, nullptr); // spec
    k_gemm<2><<<dim3(2, 512, 1), 256>>>(u, skip_w, skip_b, nullptr);       // act
    k_gemm<3><<<dim3(1, 512, 1), 256>>>(nullptr, w1, b1, nullptr);         // h
    k_gemm<4><<<dim3(2, 512, 1), 256>>>(nullptr, w2, b2, out);             // out
}